// round 9
// baseline (speedup 1.0000x reference)
#include <cuda_runtime.h>

#define BATCH 2
#define SEQ   4096
#define DM    512
#define NH    8
#define DH    64
#define MTOT  (BATCH*SEQ)   // 8192

// Scratch: projected Q/K/V (tf32-rounded fp32 bits) in [B,H,S,Dh], attn out [B,S,D]
__device__ float g_Qp[BATCH*NH*SEQ*DH];
__device__ float g_Kp[BATCH*NH*SEQ*DH];
__device__ float g_Vp[BATCH*NH*SEQ*DH];
__device__ float g_At[BATCH*SEQ*DM];

// ---------------------------------------------------------------------------
__device__ __forceinline__ unsigned f2tf(float f) {
    unsigned u;
    asm("cvt.rna.tf32.f32 %0, %1;" : "=r"(u) : "f"(f));
    return u;
}
__device__ __forceinline__ float ex2_(float x) {
    float y;
    asm("ex2.approx.f32 %0, %1;" : "=f"(y) : "f"(x));
    return y;
}
__device__ __forceinline__ void mma_tf32(float* d, const unsigned* a,
                                         unsigned b0, unsigned b1) {
    asm volatile(
        "mma.sync.aligned.m16n8k8.row.col.f32.tf32.tf32.f32 "
        "{%0,%1,%2,%3}, {%4,%5,%6,%7}, {%8,%9}, {%0,%1,%2,%3};\n"
        : "+f"(d[0]), "+f"(d[1]), "+f"(d[2]), "+f"(d[3])
        : "r"(a[0]), "r"(a[1]), "r"(a[2]), "r"(a[3]), "r"(b0), "r"(b1));
}

// ---------------------------------------------------------------------------
// NT GEMM (Round-4 config, measured fastest) — unchanged.
// ---------------------------------------------------------------------------
template <int OSEL>
__device__ __forceinline__ void gemm_body(const float* __restrict__ A,
                                          const float* __restrict__ B,
                                          float* __restrict__ C)
{
    __shared__ float sA[128][36];
    __shared__ float sB[128][36];

    const int tid = threadIdx.x;
    const int lane = tid & 31, wid = tid >> 5;
    const int g = lane >> 2, t = lane & 3;
    const int wm = wid & 1, wn = wid >> 1;          // 2x2 warp grid
    const int m0 = blockIdx.x << 7;
    const int n0 = blockIdx.y << 7;

    float acc[4][8][4];
#pragma unroll
    for (int mt = 0; mt < 4; mt++)
#pragma unroll
        for (int nt = 0; nt < 8; nt++)
#pragma unroll
            for (int c = 0; c < 4; c++) acc[mt][nt][c] = 0.f;

    const int r0 = tid >> 3;            // 0..15
    const int c4 = (tid & 7) << 2;      // 0..28 step 4

    for (int kb = 0; kb < 512; kb += 32) {
#pragma unroll
        for (int rr = 0; rr < 8; rr++) {
            int row = r0 + (rr << 4);
            float4 va = *(const float4*)(A + (size_t)(m0 + row) * 512 + kb + c4);
            float4 ta;
            ta.x = __uint_as_float(f2tf(va.x));
            ta.y = __uint_as_float(f2tf(va.y));
            ta.z = __uint_as_float(f2tf(va.z));
            ta.w = __uint_as_float(f2tf(va.w));
            *(float4*)&sA[row][c4] = ta;
            float4 vb = *(const float4*)(B + (size_t)(n0 + row) * 512 + kb + c4);
            float4 tb;
            tb.x = __uint_as_float(f2tf(vb.x));
            tb.y = __uint_as_float(f2tf(vb.y));
            tb.z = __uint_as_float(f2tf(vb.z));
            tb.w = __uint_as_float(f2tf(vb.w));
            *(float4*)&sB[row][c4] = tb;
        }
        __syncthreads();

#pragma unroll
        for (int ks = 0; ks < 4; ks++) {
            unsigned af[4][4], bf[8][2];
#pragma unroll
            for (int mt = 0; mt < 4; mt++) {
                int r = (wm << 6) + (mt << 4) + g;
                int c = (ks << 3) + t;
                af[mt][0] = __float_as_uint(sA[r][c]);
                af[mt][1] = __float_as_uint(sA[r + 8][c]);
                af[mt][2] = __float_as_uint(sA[r][c + 4]);
                af[mt][3] = __float_as_uint(sA[r + 8][c + 4]);
            }
#pragma unroll
            for (int nt = 0; nt < 8; nt++) {
                int r = (wn << 6) + (nt << 3) + g;
                int c = (ks << 3) + t;
                bf[nt][0] = __float_as_uint(sB[r][c]);
                bf[nt][1] = __float_as_uint(sB[r][c + 4]);
            }
#pragma unroll
            for (int mt = 0; mt < 4; mt++)
#pragma unroll
                for (int nt = 0; nt < 8; nt++)
                    mma_tf32(acc[mt][nt], af[mt], bf[nt][0], bf[nt][1]);
        }
        __syncthreads();
    }

#pragma unroll
    for (int mt = 0; mt < 4; mt++) {
#pragma unroll
        for (int nt = 0; nt < 8; nt++) {
            int m = m0 + (wm << 6) + (mt << 4) + g;
            int n = n0 + (wn << 6) + (nt << 3) + (t << 1);
#pragma unroll
            for (int rh = 0; rh < 2; rh++) {
                int mm = m + (rh << 3);
                float v0 = acc[mt][nt][rh * 2 + 0];
                float v1 = acc[mt][nt][rh * 2 + 1];
                if (OSEL == 0) {
                    C[(size_t)mm * 512 + n]     = v0;
                    C[(size_t)mm * 512 + n + 1] = v1;
                } else {
                    int b = mm >> 12, s = mm & 4095;
                    int h = n >> 6,  d = n & 63;
                    size_t base = (((size_t)(b * NH + h)) * SEQ + s) * DH + d;
                    C[base]     = __uint_as_float(f2tf(v0));
                    C[base + 1] = __uint_as_float(f2tf(v1));
                }
            }
        }
    }
}

__global__ __launch_bounds__(128, 2)
void gemm_proj(const float* __restrict__ q, const float* __restrict__ k,
               const float* __restrict__ v, const float* __restrict__ wq,
               const float* __restrict__ wk, const float* __restrict__ wv)
{
    const float* A; const float* B; float* C;
    if (blockIdx.z == 0)      { A = q; B = wq; C = g_Qp; }
    else if (blockIdx.z == 1) { A = k; B = wk; C = g_Kp; }
    else                      { A = v; B = wv; C = g_Vp; }
    gemm_body<1>(A, B, C);
}

__global__ __launch_bounds__(128, 2)
void gemm_out(const float* __restrict__ wo, float* __restrict__ out)
{
    gemm_body<0>(g_At, wo, out);
}

// ---------------------------------------------------------------------------
// Flash attention, tf32 mma. BQ=128, BK=32, 128 threads = 4 warps,
// warp = 32 q-rows (2 sub-blocks of 16). ALL operands in fragment-order smem:
//   Qs: 64 blocks (mt2*8+ks) x 32 lanes x f4 (stride 128)     [staged once]
//   Ps: 32 blocks (mt2*4+ks) x 32 lanes x f4 (stride 128)
//   Kf: 16 blocks (nt*4+ks2) x 32 lanes x f4, stride 132:
//       f4 = {K[nt8+g][ks2*16+t], [+4], [+8], [+12]}  (b0/b1 for 2 ks)
//   Vf: 16 blocks (nt*2+k2)  x 32 lanes x f4, stride 132:
//       f4 = {V[k2*16+t][nt8+g], V[k2*16+4+t][..], V[+8+t][..], V[+12+t][..]}
// smem: Qs 8192 | Ps 4096 | Kf 2112 | Vf 2112 = 16512 fl = 66048 B -> 3 CTA/SM
// ---------------------------------------------------------------------------
__global__ __launch_bounds__(128, 3)
void flash_tc()
{
    extern __shared__ float sm[];
    float* Qs = sm;                    // 8192 fl
    float* Ps = sm + 8192;             // 4096 fl
    float* Kf = sm + 12288;            // 2112 fl
    float* Vf = sm + 14400;            // 2112 fl
    const float4* QsF4 = (const float4*)Qs;
    const float4* PsF4 = (const float4*)Ps;
    const float4* KfF4 = (const float4*)Kf;
    const float4* VfF4 = (const float4*)Vf;

    const int tid = threadIdx.x;
    const int lane = tid & 31, w = tid >> 5;
    const int g = lane >> 2, t = lane & 3;
    const int qb = (int)(gridDim.x - 1) - (int)blockIdx.x;  // heavy tiles first
    const int q0 = qb << 7;
    const int bh = blockIdx.y;

    const float* Qb = g_Qp + (size_t)bh * SEQ * DH;
    const float* Kb = g_Kp + (size_t)bh * SEQ * DH;
    const float* Vb = g_Vp + (size_t)bh * SEQ * DH;

    // stage Q tile 128x64 into Qs in a-frag order (once per CTA)
#pragma unroll
    for (int r = 0; r < 16; r++) {
        int j = tid + (r << 7);
        int row = j >> 4, c4 = (j & 15) << 2;
        float4 vq = *(const float4*)(Qb + (size_t)(q0 + row) * DH + c4);
        int mt2 = row >> 4, rbit = (row >> 3) & 1, gg = row & 7;
        int ks = c4 >> 3, hbit = (c4 >> 2) & 1;
        int base = ((mt2 << 3) + ks) * 128 + (gg << 4) + rbit + (hbit << 1);
        Qs[base]      = vq.x;
        Qs[base + 4]  = vq.y;
        Qs[base + 8]  = vq.z;
        Qs[base + 12] = vq.w;
    }

    float o0[8][4], o1[8][4];
#pragma unroll
    for (int nt = 0; nt < 8; nt++)
#pragma unroll
        for (int c = 0; c < 4; c++) { o0[nt][c] = 0.f; o1[nt][c] = 0.f; }
    float mr[4] = {-1e30f, -1e30f, -1e30f, -1e30f};
    float lr[4] = {0.f, 0.f, 0.f, 0.f};

    const float cscale = 0.125f * 1.4426950408889634f;  // 1/sqrt(64) * log2(e)
    const int rw = w << 5;
    // P-store helpers (c-frag -> a-frag mapping), per-lane constants
    const int tp = (t < 2) ? (t << 1) : ((t << 1) - 4);
    const int ep = (t < 2) ? 0 : 2;

    const int ktmax = 4 * qb + 3;
    for (int kt = 0; kt <= ktmax; kt++) {
        __syncthreads();               // prior Kf/Vf reads done (also Q stage)
        const int k0 = kt << 5;
        // ---- stage K: row-major LDG.128, conflict-free scatter STS.32 ----
#pragma unroll
        for (int r = 0; r < 4; r++) {
            int j = tid + (r << 7);
            int row = j >> 4, ci = j & 15;
            float4 vk = *(const float4*)(Kb + (size_t)(k0 + row) * DH + (ci << 2));
            int nt = row >> 3, gg = row & 7;
            int base = ((nt << 2) + (ci >> 2)) * 132 + (gg << 4) + (ci & 3);
            Kf[base]      = vk.x;
            Kf[base + 4]  = vk.y;
            Kf[base + 8]  = vk.z;
            Kf[base + 12] = vk.w;
        }
        // ---- stage V: fragment-gather LDG.32 x4, STS.128 (warp w: blocks 4w+i)
#pragma unroll
        for (int i = 0; i < 4; i++) {
            int bb = (w << 2) + i;
            int nt = bb >> 1, k2 = bb & 1;
            const float* vsrc = Vb + (size_t)(k0 + (k2 << 4) + t) * DH + (nt << 3) + g;
            float4 vv;
            vv.x = vsrc[0];
            vv.y = vsrc[4 * DH];
            vv.z = vsrc[8 * DH];
            vv.w = vsrc[12 * DH];
            *(float4*)&Vf[bb * 132 + (lane << 2)] = vv;
        }
        __syncthreads();

        // warp-level early-out: chunk fully above this warp's diagonal
        const int kvb = kt << 5;
        if (kvb > q0 + rw + 31) continue;

        // ---- S = Q K^T : ks2 outer, all LDS.128; each Kf f4 feeds 4 mmas ----
        float s0[4][4], s1[4][4];
#pragma unroll
        for (int nt = 0; nt < 4; nt++)
#pragma unroll
            for (int c = 0; c < 4; c++) { s0[nt][c] = 0.f; s1[nt][c] = 0.f; }
#pragma unroll
        for (int ks2 = 0; ks2 < 4; ks2++) {
            float4 qa0 = QsF4[(((w << 1)    ) * 8 + 2 * ks2    ) * 32 + lane];
            float4 qb0_ = QsF4[(((w << 1)    ) * 8 + 2 * ks2 + 1) * 32 + lane];
            float4 qa1 = QsF4[(((w << 1) + 1) * 8 + 2 * ks2    ) * 32 + lane];
            float4 qb1_ = QsF4[(((w << 1) + 1) * 8 + 2 * ks2 + 1) * 32 + lane];
            unsigned qfA0[4] = {__float_as_uint(qa0.x), __float_as_uint(qa0.y),
                                __float_as_uint(qa0.z), __float_as_uint(qa0.w)};
            unsigned qfB0[4] = {__float_as_uint(qb0_.x), __float_as_uint(qb0_.y),
                                __float_as_uint(qb0_.z), __float_as_uint(qb0_.w)};
            unsigned qfA1[4] = {__float_as_uint(qa1.x), __float_as_uint(qa1.y),
                                __float_as_uint(qa1.z), __float_as_uint(qa1.w)};
            unsigned qfB1[4] = {__float_as_uint(qb1_.x), __float_as_uint(qb1_.y),
                                __float_as_uint(qb1_.z), __float_as_uint(qb1_.w)};
#pragma unroll
            for (int nt = 0; nt < 4; nt++) {
                float4 kf = KfF4[((nt << 2) + ks2) * 33 + lane];
                unsigned b0 = __float_as_uint(kf.x), b1 = __float_as_uint(kf.y);
                unsigned b2 = __float_as_uint(kf.z), b3 = __float_as_uint(kf.w);
                mma_tf32(s0[nt], qfA0, b0, b1);
                mma_tf32(s0[nt], qfB0, b2, b3);
                mma_tf32(s1[nt], qfA1, b0, b1);
                mma_tf32(s1[nt], qfB1, b2, b3);
            }
        }

        // ---- scale + causal mask ----
#pragma unroll
        for (int nt = 0; nt < 4; nt++)
#pragma unroll
            for (int c = 0; c < 4; c++) { s0[nt][c] *= cscale; s1[nt][c] *= cscale; }
        if (kt >= 4 * qb) {
            const int qg0 = q0 + rw + g;
#pragma unroll
            for (int nt = 0; nt < 4; nt++) {
                int kv = kvb + (nt << 3) + (t << 1);
                if (kv > qg0)          s0[nt][0] = -1e30f;
                if (kv + 1 > qg0)      s0[nt][1] = -1e30f;
                if (kv > qg0 + 8)      s0[nt][2] = -1e30f;
                if (kv + 1 > qg0 + 8)  s0[nt][3] = -1e30f;
                if (kv > qg0 + 16)     s1[nt][0] = -1e30f;
                if (kv + 1 > qg0 + 16) s1[nt][1] = -1e30f;
                if (kv > qg0 + 24)     s1[nt][2] = -1e30f;
                if (kv + 1 > qg0 + 24) s1[nt][3] = -1e30f;
            }
        }

        // ---- online softmax (4 row-sets) ----
#pragma unroll
        for (int sb = 0; sb < 2; sb++) {
            float (*s)[4] = sb ? s1 : s0;
            float (*o)[4] = sb ? o1 : o0;
#pragma unroll
            for (int r = 0; r < 2; r++) {
                int ix = sb * 2 + r;
                float mx = -1e30f;
#pragma unroll
                for (int nt = 0; nt < 4; nt++)
                    mx = fmaxf(mx, fmaxf(s[nt][2 * r], s[nt][2 * r + 1]));
                mx = fmaxf(mx, __shfl_xor_sync(0xffffffffu, mx, 1));
                mx = fmaxf(mx, __shfl_xor_sync(0xffffffffu, mx, 2));
                float mn = fmaxf(mr[ix], mx);
                float al = ex2_(mr[ix] - mn);
                mr[ix] = mn;
                float rs = 0.f;
#pragma unroll
                for (int nt = 0; nt < 4; nt++) {
                    float p0 = ex2_(s[nt][2 * r] - mn);
                    float p1 = ex2_(s[nt][2 * r + 1] - mn);
                    s[nt][2 * r] = p0; s[nt][2 * r + 1] = p1;
                    rs += p0 + p1;
                }
                rs += __shfl_xor_sync(0xffffffffu, rs, 1);
                rs += __shfl_xor_sync(0xffffffffu, rs, 2);
                lr[ix] = lr[ix] * al + rs;
#pragma unroll
                for (int nt = 0; nt < 8; nt++) {
                    o[nt][2 * r]     *= al;
                    o[nt][2 * r + 1] *= al;
                }
            }
        }

        // ---- store P (tf32) in a-frag order: 2 STS.64 per (sb,nt) ----
#pragma unroll
        for (int sb = 0; sb < 2; sb++) {
            float (*s)[4] = sb ? s1 : s0;
            const int mt2 = (w << 1) + sb;
#pragma unroll
            for (int nt = 0; nt < 4; nt++) {
                int base = ((mt2 << 2) + nt) * 128 + (g << 4) + ep;
                float2 lo = make_float2(__uint_as_float(f2tf(s[nt][0])),
                                        __uint_as_float(f2tf(s[nt][2])));
                float2 hi = make_float2(__uint_as_float(f2tf(s[nt][1])),
                                        __uint_as_float(f2tf(s[nt][3])));
                *(float2*)&Ps[base + (tp << 2)]       = lo;
                *(float2*)&Ps[base + ((tp + 1) << 2)] = hi;
            }
        }
        __syncwarp();

        // ---- O += P V : k2 outer, all LDS.128; each Vf f4 feeds 4 mmas ----
#pragma unroll
        for (int k2 = 0; k2 < 2; k2++) {
            float4 pa0 = PsF4[(((w << 1)    ) * 4 + 2 * k2    ) * 32 + lane];
            float4 pb0_ = PsF4[(((w << 1)    ) * 4 + 2 * k2 + 1) * 32 + lane];
            float4 pa1 = PsF4[(((w << 1) + 1) * 4 + 2 * k2    ) * 32 + lane];
            float4 pb1_ = PsF4[(((w << 1) + 1) * 4 + 2 * k2 + 1) * 32 + lane];
            unsigned pfA0[4] = {__float_as_uint(pa0.x), __float_as_uint(pa0.y),
                                __float_as_uint(pa0.z), __float_as_uint(pa0.w)};
            unsigned pfB0[4] = {__float_as_uint(pb0_.x), __float_as_uint(pb0_.y),
                                __float_as_uint(pb0_.z), __float_as_uint(pb0_.w)};
            unsigned pfA1[4] = {__float_as_uint(pa1.x), __float_as_uint(pa1.y),
                                __float_as_uint(pa1.z), __float_as_uint(pa1.w)};
            unsigned pfB1[4] = {__float_as_uint(pb1_.x), __float_as_uint(pb1_.y),
                                __float_as_uint(pb1_.z), __float_as_uint(pb1_.w)};
#pragma unroll
            for (int nt = 0; nt < 8; nt++) {
                float4 vf = VfF4[((nt << 1) + k2) * 33 + lane];
                unsigned v0 = __float_as_uint(vf.x), v1 = __float_as_uint(vf.y);
                unsigned v2 = __float_as_uint(vf.z), v3 = __float_as_uint(vf.w);
                mma_tf32(o0[nt], pfA0, v0, v1);
                mma_tf32(o0[nt], pfB0, v2, v3);
                mma_tf32(o1[nt], pfA1, v0, v1);
                mma_tf32(o1[nt], pfB1, v2, v3);
            }
        }
    }

    // ---- epilogue -> g_At [B, S, H*Dh] (plain fp32) ----
    const int b = bh >> 3, h = bh & 7;
#pragma unroll
    for (int sb = 0; sb < 2; sb++) {
        float (*o)[4] = sb ? o1 : o0;
#pragma unroll
        for (int r = 0; r < 2; r++) {
            int row = q0 + rw + (sb << 4) + (r << 3) + g;
            float inv = 1.f / lr[sb * 2 + r];
#pragma unroll
            for (int nt = 0; nt < 8; nt++) {
                int col = (h << 6) + (nt << 3) + (t << 1);
                size_t base = ((size_t)b * SEQ + row) * DM + col;
                float2 v = make_float2(o[nt][2 * r] * inv, o[nt][2 * r + 1] * inv);
                *(float2*)&g_At[base] = v;
            }
        }
    }
}

// ---------------------------------------------------------------------------
extern "C" void kernel_launch(void* const* d_in, const int* in_sizes, int n_in,
                              void* d_out, int out_size)
{
    const float* q  = (const float*)d_in[0];
    const float* k  = (const float*)d_in[1];
    const float* v  = (const float*)d_in[2];
    const float* wq = (const float*)d_in[3];
    const float* wk = (const float*)d_in[4];
    const float* wv = (const float*)d_in[5];
    const float* wo = (const float*)d_in[6];
    float* out = (float*)d_out;

    const int FLASH_SMEM = 16512 * (int)sizeof(float);   // 66048 B -> 3 CTA/SM
    cudaFuncSetAttribute(flash_tc, cudaFuncAttributeMaxDynamicSharedMemorySize,
                         FLASH_SMEM);

    dim3 pg(MTOT / 128, DM / 128, 3);        // 64 x 4 x 3
    gemm_proj<<<pg, 128>>>(q, k, v, wq, wk, wv);

    dim3 fg(SEQ / 128, BATCH * NH);          // 32 x 16
    flash_tc<<<fg, 128, FLASH_SMEM>>>();

    dim3 og(MTOT / 128, DM / 128);           // 64 x 4
    gemm_out<<<og, 128>>>(wo, out);
}

// round 10
// speedup vs baseline: 1.0612x; 1.0612x over previous
#include <cuda_runtime.h>

#define BATCH 2
#define SEQ   4096
#define DM    512
#define NH    8
#define DH    64
#define MTOT  (BATCH*SEQ)   // 8192

// Scratch: projected Q/K/V (tf32-rounded fp32 bits) in [B,H,S,Dh], attn out [B,S,D]
__device__ float g_Qp[BATCH*NH*SEQ*DH];
__device__ float g_Kp[BATCH*NH*SEQ*DH];
__device__ float g_Vp[BATCH*NH*SEQ*DH];
__device__ float g_At[BATCH*SEQ*DM];

// ---------------------------------------------------------------------------
__device__ __forceinline__ unsigned f2tf(float f) {
    unsigned u;
    asm("cvt.rna.tf32.f32 %0, %1;" : "=r"(u) : "f"(f));
    return u;
}
__device__ __forceinline__ float ex2_(float x) {
    float y;
    asm("ex2.approx.f32 %0, %1;" : "=f"(y) : "f"(x));
    return y;
}
__device__ __forceinline__ void mma_tf32(float* d, const unsigned* a,
                                         unsigned b0, unsigned b1) {
    asm volatile(
        "mma.sync.aligned.m16n8k8.row.col.f32.tf32.tf32.f32 "
        "{%0,%1,%2,%3}, {%4,%5,%6,%7}, {%8,%9}, {%0,%1,%2,%3};\n"
        : "+f"(d[0]), "+f"(d[1]), "+f"(d[2]), "+f"(d[3])
        : "r"(a[0]), "r"(a[1]), "r"(a[2]), "r"(a[3]), "r"(b0), "r"(b1));
}

// ---------------------------------------------------------------------------
// NT GEMM (Round-4 config, measured fastest) — unchanged.
// ---------------------------------------------------------------------------
template <int OSEL>
__device__ __forceinline__ void gemm_body(const float* __restrict__ A,
                                          const float* __restrict__ B,
                                          float* __restrict__ C)
{
    __shared__ float sA[128][36];
    __shared__ float sB[128][36];

    const int tid = threadIdx.x;
    const int lane = tid & 31, wid = tid >> 5;
    const int g = lane >> 2, t = lane & 3;
    const int wm = wid & 1, wn = wid >> 1;          // 2x2 warp grid
    const int m0 = blockIdx.x << 7;
    const int n0 = blockIdx.y << 7;

    float acc[4][8][4];
#pragma unroll
    for (int mt = 0; mt < 4; mt++)
#pragma unroll
        for (int nt = 0; nt < 8; nt++)
#pragma unroll
            for (int c = 0; c < 4; c++) acc[mt][nt][c] = 0.f;

    const int r0 = tid >> 3;            // 0..15
    const int c4 = (tid & 7) << 2;      // 0..28 step 4

    for (int kb = 0; kb < 512; kb += 32) {
#pragma unroll
        for (int rr = 0; rr < 8; rr++) {
            int row = r0 + (rr << 4);
            float4 va = *(const float4*)(A + (size_t)(m0 + row) * 512 + kb + c4);
            float4 ta;
            ta.x = __uint_as_float(f2tf(va.x));
            ta.y = __uint_as_float(f2tf(va.y));
            ta.z = __uint_as_float(f2tf(va.z));
            ta.w = __uint_as_float(f2tf(va.w));
            *(float4*)&sA[row][c4] = ta;
            float4 vb = *(const float4*)(B + (size_t)(n0 + row) * 512 + kb + c4);
            float4 tb;
            tb.x = __uint_as_float(f2tf(vb.x));
            tb.y = __uint_as_float(f2tf(vb.y));
            tb.z = __uint_as_float(f2tf(vb.z));
            tb.w = __uint_as_float(f2tf(vb.w));
            *(float4*)&sB[row][c4] = tb;
        }
        __syncthreads();

#pragma unroll
        for (int ks = 0; ks < 4; ks++) {
            unsigned af[4][4], bf[8][2];
#pragma unroll
            for (int mt = 0; mt < 4; mt++) {
                int r = (wm << 6) + (mt << 4) + g;
                int c = (ks << 3) + t;
                af[mt][0] = __float_as_uint(sA[r][c]);
                af[mt][1] = __float_as_uint(sA[r + 8][c]);
                af[mt][2] = __float_as_uint(sA[r][c + 4]);
                af[mt][3] = __float_as_uint(sA[r + 8][c + 4]);
            }
#pragma unroll
            for (int nt = 0; nt < 8; nt++) {
                int r = (wn << 6) + (nt << 3) + g;
                int c = (ks << 3) + t;
                bf[nt][0] = __float_as_uint(sB[r][c]);
                bf[nt][1] = __float_as_uint(sB[r][c + 4]);
            }
#pragma unroll
            for (int mt = 0; mt < 4; mt++)
#pragma unroll
                for (int nt = 0; nt < 8; nt++)
                    mma_tf32(acc[mt][nt], af[mt], bf[nt][0], bf[nt][1]);
        }
        __syncthreads();
    }

#pragma unroll
    for (int mt = 0; mt < 4; mt++) {
#pragma unroll
        for (int nt = 0; nt < 8; nt++) {
            int m = m0 + (wm << 6) + (mt << 4) + g;
            int n = n0 + (wn << 6) + (nt << 3) + (t << 1);
#pragma unroll
            for (int rh = 0; rh < 2; rh++) {
                int mm = m + (rh << 3);
                float v0 = acc[mt][nt][rh * 2 + 0];
                float v1 = acc[mt][nt][rh * 2 + 1];
                if (OSEL == 0) {
                    C[(size_t)mm * 512 + n]     = v0;
                    C[(size_t)mm * 512 + n + 1] = v1;
                } else {
                    int b = mm >> 12, s = mm & 4095;
                    int h = n >> 6,  d = n & 63;
                    size_t base = (((size_t)(b * NH + h)) * SEQ + s) * DH + d;
                    C[base]     = __uint_as_float(f2tf(v0));
                    C[base + 1] = __uint_as_float(f2tf(v1));
                }
            }
        }
    }
}

__global__ __launch_bounds__(128, 2)
void gemm_proj(const float* __restrict__ q, const float* __restrict__ k,
               const float* __restrict__ v, const float* __restrict__ wq,
               const float* __restrict__ wk, const float* __restrict__ wv)
{
    const float* A; const float* B; float* C;
    if (blockIdx.z == 0)      { A = q; B = wq; C = g_Qp; }
    else if (blockIdx.z == 1) { A = k; B = wk; C = g_Kp; }
    else                      { A = v; B = wv; C = g_Vp; }
    gemm_body<1>(A, B, C);
}

__global__ __launch_bounds__(128, 2)
void gemm_out(const float* __restrict__ wo, float* __restrict__ out)
{
    gemm_body<0>(g_At, wo, out);
}

// ---------------------------------------------------------------------------
// Flash attention, tf32 mma (Round-8 layout = best measured). BQ=128, BK=32,
// 128 threads = 4 warps, warp = 32 q-rows (2 sub-blocks of 16), ks-outer.
// Q and P in a-fragment-order smem (LDS.128 operand fetch); K/V row-major.
// NEW: warp-uniform ballot skip of the softmax rescale when no lane saw a
// new running max (al==1 -> skip is bit-identical).
// smem (floats): Qs 8192 @0 | Ps 4096 @8192 | sK 32x68 @12288 |
//                sV 32x72 @14464 ; total 16768 fl = 67072 B -> 3 CTA/SM.
// ---------------------------------------------------------------------------
__global__ __launch_bounds__(128, 3)
void flash_tc()
{
    extern __shared__ float sm[];
    float* Qs = sm;                    // frag-order, 8192 fl
    float* Ps = sm + 8192;             // frag-order, 4096 fl
    float* sK = sm + 12288;            // [32][68]
    float* sV = sm + 14464;            // [32][72]
    const float4* QsF4 = (const float4*)Qs;
    const float4* PsF4 = (const float4*)Ps;

    const int tid = threadIdx.x;
    const int lane = tid & 31, w = tid >> 5;
    const int g = lane >> 2, t = lane & 3;
    const int qb = (int)(gridDim.x - 1) - (int)blockIdx.x;  // heavy tiles first
    const int q0 = qb << 7;
    const int bh = blockIdx.y;

    const float* Qb = g_Qp + (size_t)bh * SEQ * DH;
    const float* Kb = g_Kp + (size_t)bh * SEQ * DH;
    const float* Vb = g_Vp + (size_t)bh * SEQ * DH;

    // stage Q tile 128x64 into Qs in a-frag order (once per CTA)
#pragma unroll
    for (int r = 0; r < 16; r++) {
        int j = tid + (r << 7);
        int row = j >> 4, c4 = (j & 15) << 2;
        float4 vq = *(const float4*)(Qb + (size_t)(q0 + row) * DH + c4);
        int mt2 = row >> 4, rbit = (row >> 3) & 1, gg = row & 7;
        int ks = c4 >> 3, hbit = (c4 >> 2) & 1;
        int base = ((mt2 << 3) + ks) * 128 + (gg << 4) + rbit + (hbit << 1);
        Qs[base]      = vq.x;
        Qs[base + 4]  = vq.y;
        Qs[base + 8]  = vq.z;
        Qs[base + 12] = vq.w;
    }

    float o0[8][4], o1[8][4];
#pragma unroll
    for (int nt = 0; nt < 8; nt++)
#pragma unroll
        for (int c = 0; c < 4; c++) { o0[nt][c] = 0.f; o1[nt][c] = 0.f; }
    float mr[4] = {-1e30f, -1e30f, -1e30f, -1e30f};
    float lr[4] = {0.f, 0.f, 0.f, 0.f};

    const float cscale = 0.125f * 1.4426950408889634f;  // 1/sqrt(64) * log2(e)
    const int rw = w << 5;
    // P-store helpers (c-frag -> a-frag mapping), per-lane constants
    const int tp = (t < 2) ? (t << 1) : ((t << 1) - 4);
    const int ep = (t < 2) ? 0 : 2;

    const int ktmax = 4 * qb + 3;
    for (int kt = 0; kt <= ktmax; kt++) {
        __syncthreads();               // prior sK/sV reads done (also Q stage)
        {   // stage K, V chunk (32x64 each), row-major padded
            const int k0 = kt << 5;
#pragma unroll
            for (int r = 0; r < 4; r++) {
                int j = tid + (r << 7);
                int row = j >> 4, c4 = (j & 15) << 2;
                *(float4*)&sK[row * 68 + c4] =
                    *(const float4*)(Kb + (size_t)(k0 + row) * DH + c4);
                *(float4*)&sV[row * 72 + c4] =
                    *(const float4*)(Vb + (size_t)(k0 + row) * DH + c4);
            }
        }
        __syncthreads();

        // warp-level early-out: chunk fully above this warp's diagonal
        const int kvb = kt << 5;
        if (kvb > q0 + rw + 31) continue;

        // ---- S = Q K^T (32q x 32kv per warp), ks outer, LDS.128 Q frags ----
        float s0[4][4], s1[4][4];
#pragma unroll
        for (int nt = 0; nt < 4; nt++)
#pragma unroll
            for (int c = 0; c < 4; c++) { s0[nt][c] = 0.f; s1[nt][c] = 0.f; }
#pragma unroll
        for (int ks = 0; ks < 8; ks++) {
            const int c = (ks << 3) + t;
            float4 qv0 = QsF4[(((w << 1) << 3) + ks) * 32 + lane];
            float4 qv1 = QsF4[((((w << 1) + 1) << 3) + ks) * 32 + lane];
            unsigned qf0[4] = {__float_as_uint(qv0.x), __float_as_uint(qv0.y),
                               __float_as_uint(qv0.z), __float_as_uint(qv0.w)};
            unsigned qf1[4] = {__float_as_uint(qv1.x), __float_as_uint(qv1.y),
                               __float_as_uint(qv1.z), __float_as_uint(qv1.w)};
#pragma unroll
            for (int nt = 0; nt < 4; nt++) {
                int r = (nt << 3) + g;
                unsigned b0 = __float_as_uint(sK[r * 68 + c]);
                unsigned b1 = __float_as_uint(sK[r * 68 + c + 4]);
                mma_tf32(s0[nt], qf0, b0, b1);
                mma_tf32(s1[nt], qf1, b0, b1);
            }
        }

        // ---- scale + causal mask ----
#pragma unroll
        for (int nt = 0; nt < 4; nt++)
#pragma unroll
            for (int c = 0; c < 4; c++) { s0[nt][c] *= cscale; s1[nt][c] *= cscale; }
        if (kt >= 4 * qb) {
            const int qg0 = q0 + rw + g;
#pragma unroll
            for (int nt = 0; nt < 4; nt++) {
                int kv = kvb + (nt << 3) + (t << 1);
                if (kv > qg0)          s0[nt][0] = -1e30f;
                if (kv + 1 > qg0)      s0[nt][1] = -1e30f;
                if (kv > qg0 + 8)      s0[nt][2] = -1e30f;
                if (kv + 1 > qg0 + 8)  s0[nt][3] = -1e30f;
                if (kv > qg0 + 16)     s1[nt][0] = -1e30f;
                if (kv + 1 > qg0 + 16) s1[nt][1] = -1e30f;
                if (kv > qg0 + 24)     s1[nt][2] = -1e30f;
                if (kv + 1 > qg0 + 24) s1[nt][3] = -1e30f;
            }
        }

        // ---- online softmax (4 row-sets), ballot-skip rescale ----
#pragma unroll
        for (int sb = 0; sb < 2; sb++) {
            float (*s)[4] = sb ? s1 : s0;
            float (*o)[4] = sb ? o1 : o0;
#pragma unroll
            for (int r = 0; r < 2; r++) {
                int ix = sb * 2 + r;
                float mx = -1e30f;
#pragma unroll
                for (int nt = 0; nt < 4; nt++)
                    mx = fmaxf(mx, fmaxf(s[nt][2 * r], s[nt][2 * r + 1]));
                mx = fmaxf(mx, __shfl_xor_sync(0xffffffffu, mx, 1));
                mx = fmaxf(mx, __shfl_xor_sync(0xffffffffu, mx, 2));
                unsigned newmax = __ballot_sync(0xffffffffu, mx > mr[ix]);
                float mn = fmaxf(mr[ix], mx);
                float rs = 0.f;
#pragma unroll
                for (int nt = 0; nt < 4; nt++) {
                    float p0 = ex2_(s[nt][2 * r] - mn);
                    float p1 = ex2_(s[nt][2 * r + 1] - mn);
                    s[nt][2 * r] = p0; s[nt][2 * r + 1] = p1;
                    rs += p0 + p1;
                }
                rs += __shfl_xor_sync(0xffffffffu, rs, 1);
                rs += __shfl_xor_sync(0xffffffffu, rs, 2);
                if (newmax) {
                    // some lane's running max changed: full rescale path
                    float al = ex2_(mr[ix] - mn);
                    mr[ix] = mn;
                    lr[ix] = lr[ix] * al + rs;
#pragma unroll
                    for (int nt = 0; nt < 8; nt++) {
                        o[nt][2 * r]     *= al;
                        o[nt][2 * r + 1] *= al;
                    }
                } else {
                    // mn == mr[ix] for every lane: al == 1, skip (bit-identical)
                    lr[ix] += rs;
                }
            }
        }

        // ---- store P (tf32) in a-frag order: 2 STS.64 per (sb,nt) ----
#pragma unroll
        for (int sb = 0; sb < 2; sb++) {
            float (*s)[4] = sb ? s1 : s0;
            const int mt2 = (w << 1) + sb;
#pragma unroll
            for (int nt = 0; nt < 4; nt++) {
                int base = ((mt2 << 2) + nt) * 128 + (g << 4) + ep;
                float2 lo = make_float2(__uint_as_float(f2tf(s[nt][0])),
                                        __uint_as_float(f2tf(s[nt][2])));
                float2 hi = make_float2(__uint_as_float(f2tf(s[nt][1])),
                                        __uint_as_float(f2tf(s[nt][3])));
                *(float2*)&Ps[base + (tp << 2)]       = lo;
                *(float2*)&Ps[base + ((tp + 1) << 2)] = hi;
            }
        }
        __syncwarp();

        // ---- O += P V : ks outer over 32 kv rows, LDS.128 P frags ----
#pragma unroll
        for (int ks = 0; ks < 4; ks++) {
            float4 pv0 = PsF4[((((w << 1)) << 2) + ks) * 32 + lane];
            float4 pv1 = PsF4[((((w << 1) + 1) << 2) + ks) * 32 + lane];
            unsigned pf0[4] = {__float_as_uint(pv0.x), __float_as_uint(pv0.y),
                               __float_as_uint(pv0.z), __float_as_uint(pv0.w)};
            unsigned pf1[4] = {__float_as_uint(pv1.x), __float_as_uint(pv1.y),
                               __float_as_uint(pv1.z), __float_as_uint(pv1.w)};
            const int kr = (ks << 3) + t;
#pragma unroll
            for (int nt = 0; nt < 8; nt++) {
                int nc = (nt << 3) + g;
                unsigned v0 = __float_as_uint(sV[kr * 72 + nc]);
                unsigned v1 = __float_as_uint(sV[(kr + 4) * 72 + nc]);
                mma_tf32(o0[nt], pf0, v0, v1);
                mma_tf32(o1[nt], pf1, v0, v1);
            }
        }
    }

    // ---- epilogue -> g_At [B, S, H*Dh] (plain fp32) ----
    const int b = bh >> 3, h = bh & 7;
#pragma unroll
    for (int sb = 0; sb < 2; sb++) {
        float (*o)[4] = sb ? o1 : o0;
#pragma unroll
        for (int r = 0; r < 2; r++) {
            int row = q0 + rw + (sb << 4) + (r << 3) + g;
            float inv = 1.f / lr[sb * 2 + r];
#pragma unroll
            for (int nt = 0; nt < 8; nt++) {
                int col = (h << 6) + (nt << 3) + (t << 1);
                size_t base = ((size_t)b * SEQ + row) * DM + col;
                float2 v = make_float2(o[nt][2 * r] * inv, o[nt][2 * r + 1] * inv);
                *(float2*)&g_At[base] = v;
            }
        }
    }
}

// ---------------------------------------------------------------------------
extern "C" void kernel_launch(void* const* d_in, const int* in_sizes, int n_in,
                              void* d_out, int out_size)
{
    const float* q  = (const float*)d_in[0];
    const float* k  = (const float*)d_in[1];
    const float* v  = (const float*)d_in[2];
    const float* wq = (const float*)d_in[3];
    const float* wk = (const float*)d_in[4];
    const float* wv = (const float*)d_in[5];
    const float* wo = (const float*)d_in[6];
    float* out = (float*)d_out;

    const int FLASH_SMEM = 16768 * (int)sizeof(float);   // 67072 B -> 3 CTA/SM
    cudaFuncSetAttribute(flash_tc, cudaFuncAttributeMaxDynamicSharedMemorySize,
                         FLASH_SMEM);

    dim3 pg(MTOT / 128, DM / 128, 3);        // 64 x 4 x 3
    gemm_proj<<<pg, 128>>>(q, k, v, wq, wk, wv);

    dim3 fg(SEQ / 128, BATCH * NH);          // 32 x 16
    flash_tc<<<fg, 128, FLASH_SMEM>>>();

    dim3 og(MTOT / 128, DM / 128);           // 64 x 4
    gemm_out<<<og, 128>>>(wo, out);
}

// round 11
// speedup vs baseline: 1.1602x; 1.0933x over previous
#include <cuda_runtime.h>
#include <stdint.h>

#define BATCH 2
#define SEQ   4096
#define DM    512
#define NH    8
#define DH    64
#define MTOT  (BATCH*SEQ)   // 8192

// Scratch: projected Q/K/V (tf32-rounded fp32 bits) in [B,H,S,Dh], attn out [B,S,D]
__device__ float g_Qp[BATCH*NH*SEQ*DH];
__device__ float g_Kp[BATCH*NH*SEQ*DH];
__device__ float g_Vp[BATCH*NH*SEQ*DH];
__device__ float g_At[BATCH*SEQ*DM];

// ---------------------------------------------------------------------------
__device__ __forceinline__ unsigned f2tf(float f) {
    unsigned u;
    asm("cvt.rna.tf32.f32 %0, %1;" : "=r"(u) : "f"(f));
    return u;
}
__device__ __forceinline__ float ex2_(float x) {
    float y;
    asm("ex2.approx.f32 %0, %1;" : "=f"(y) : "f"(x));
    return y;
}
__device__ __forceinline__ void mma_tf32(float* d, const unsigned* a,
                                         unsigned b0, unsigned b1) {
    asm volatile(
        "mma.sync.aligned.m16n8k8.row.col.f32.tf32.tf32.f32 "
        "{%0,%1,%2,%3}, {%4,%5,%6,%7}, {%8,%9}, {%0,%1,%2,%3};\n"
        : "+f"(d[0]), "+f"(d[1]), "+f"(d[2]), "+f"(d[3])
        : "r"(a[0]), "r"(a[1]), "r"(a[2]), "r"(a[3]), "r"(b0), "r"(b1));
}
__device__ __forceinline__ uint32_t smem_u32(const void* p) {
    return (uint32_t)__cvta_generic_to_shared(p);
}
__device__ __forceinline__ void cp16(uint32_t d, const void* s) {
    asm volatile("cp.async.cg.shared.global [%0], [%1], 16;\n" :: "r"(d), "l"(s));
}
#define CP_COMMIT() asm volatile("cp.async.commit_group;\n" ::: "memory")
#define CP_WAIT0()  asm volatile("cp.async.wait_group 0;\n" ::: "memory")
#define CP_WAIT1()  asm volatile("cp.async.wait_group 1;\n" ::: "memory")

// ---------------------------------------------------------------------------
// NT GEMM (Round-4 config, measured fastest) — unchanged.
// ---------------------------------------------------------------------------
template <int OSEL>
__device__ __forceinline__ void gemm_body(const float* __restrict__ A,
                                          const float* __restrict__ B,
                                          float* __restrict__ C)
{
    __shared__ float sA[128][36];
    __shared__ float sB[128][36];

    const int tid = threadIdx.x;
    const int lane = tid & 31, wid = tid >> 5;
    const int g = lane >> 2, t = lane & 3;
    const int wm = wid & 1, wn = wid >> 1;          // 2x2 warp grid
    const int m0 = blockIdx.x << 7;
    const int n0 = blockIdx.y << 7;

    float acc[4][8][4];
#pragma unroll
    for (int mt = 0; mt < 4; mt++)
#pragma unroll
        for (int nt = 0; nt < 8; nt++)
#pragma unroll
            for (int c = 0; c < 4; c++) acc[mt][nt][c] = 0.f;

    const int r0 = tid >> 3;            // 0..15
    const int c4 = (tid & 7) << 2;      // 0..28 step 4

    for (int kb = 0; kb < 512; kb += 32) {
#pragma unroll
        for (int rr = 0; rr < 8; rr++) {
            int row = r0 + (rr << 4);
            float4 va = *(const float4*)(A + (size_t)(m0 + row) * 512 + kb + c4);
            float4 ta;
            ta.x = __uint_as_float(f2tf(va.x));
            ta.y = __uint_as_float(f2tf(va.y));
            ta.z = __uint_as_float(f2tf(va.z));
            ta.w = __uint_as_float(f2tf(va.w));
            *(float4*)&sA[row][c4] = ta;
            float4 vb = *(const float4*)(B + (size_t)(n0 + row) * 512 + kb + c4);
            float4 tb;
            tb.x = __uint_as_float(f2tf(vb.x));
            tb.y = __uint_as_float(f2tf(vb.y));
            tb.z = __uint_as_float(f2tf(vb.z));
            tb.w = __uint_as_float(f2tf(vb.w));
            *(float4*)&sB[row][c4] = tb;
        }
        __syncthreads();

#pragma unroll
        for (int ks = 0; ks < 4; ks++) {
            unsigned af[4][4], bf[8][2];
#pragma unroll
            for (int mt = 0; mt < 4; mt++) {
                int r = (wm << 6) + (mt << 4) + g;
                int c = (ks << 3) + t;
                af[mt][0] = __float_as_uint(sA[r][c]);
                af[mt][1] = __float_as_uint(sA[r + 8][c]);
                af[mt][2] = __float_as_uint(sA[r][c + 4]);
                af[mt][3] = __float_as_uint(sA[r + 8][c + 4]);
            }
#pragma unroll
            for (int nt = 0; nt < 8; nt++) {
                int r = (wn << 6) + (nt << 3) + g;
                int c = (ks << 3) + t;
                bf[nt][0] = __float_as_uint(sB[r][c]);
                bf[nt][1] = __float_as_uint(sB[r][c + 4]);
            }
#pragma unroll
            for (int mt = 0; mt < 4; mt++)
#pragma unroll
                for (int nt = 0; nt < 8; nt++)
                    mma_tf32(acc[mt][nt], af[mt], bf[nt][0], bf[nt][1]);
        }
        __syncthreads();
    }

#pragma unroll
    for (int mt = 0; mt < 4; mt++) {
#pragma unroll
        for (int nt = 0; nt < 8; nt++) {
            int m = m0 + (wm << 6) + (mt << 4) + g;
            int n = n0 + (wn << 6) + (nt << 3) + (t << 1);
#pragma unroll
            for (int rh = 0; rh < 2; rh++) {
                int mm = m + (rh << 3);
                float v0 = acc[mt][nt][rh * 2 + 0];
                float v1 = acc[mt][nt][rh * 2 + 1];
                if (OSEL == 0) {
                    C[(size_t)mm * 512 + n]     = v0;
                    C[(size_t)mm * 512 + n + 1] = v1;
                } else {
                    int b = mm >> 12, s = mm & 4095;
                    int h = n >> 6,  d = n & 63;
                    size_t base = (((size_t)(b * NH + h)) * SEQ + s) * DH + d;
                    C[base]     = __uint_as_float(f2tf(v0));
                    C[base + 1] = __uint_as_float(f2tf(v1));
                }
            }
        }
    }
}

__global__ __launch_bounds__(128, 2)
void gemm_proj(const float* __restrict__ q, const float* __restrict__ k,
               const float* __restrict__ v, const float* __restrict__ wq,
               const float* __restrict__ wk, const float* __restrict__ wv)
{
    const float* A; const float* B; float* C;
    if (blockIdx.z == 0)      { A = q; B = wq; C = g_Qp; }
    else if (blockIdx.z == 1) { A = k; B = wk; C = g_Kp; }
    else                      { A = v; B = wv; C = g_Vp; }
    gemm_body<1>(A, B, C);
}

__global__ __launch_bounds__(128, 2)
void gemm_out(const float* __restrict__ wo, float* __restrict__ out)
{
    gemm_body<0>(g_At, wo, out);
}

// ---------------------------------------------------------------------------
// Flash attention, tf32 mma. BQ=128, BK=32, 128 threads = 4 warps,
// warp = 32 q-rows (2 sub-blocks of 16), ks-outer.
// Changes vs R8 (best): (1) P exchanged c-frag->a-frag via shfl within each
// 4-lane quad (no Ps smem, no STS/LDS roundtrip, bit-identical values);
// (2) cp.async double-buffered K/V with one-chunk lookahead (wait_group 1).
// smem (floats): Qs frag-order 8192 @0 | sK 2x32x68 @8192 | sV 2x32x72 @12544
// total 17152 fl = 68608 B -> 3 CTA/SM.
// ---------------------------------------------------------------------------
__global__ __launch_bounds__(128, 3)
void flash_tc()
{
    extern __shared__ float sm[];
    float* Qs  = sm;                   // frag-order, 8192 fl
    float* sKb = sm + 8192;            // [2][32][68]
    float* sVb = sm + 12544;           // [2][32][72]
    const float4* QsF4 = (const float4*)Qs;

    const int tid = threadIdx.x;
    const int lane = tid & 31, w = tid >> 5;
    const int g = lane >> 2, t = lane & 3;
    const int qb = (int)(gridDim.x - 1) - (int)blockIdx.x;  // heavy tiles first
    const int q0 = qb << 7;
    const int bh = blockIdx.y;

    const float* Qb = g_Qp + (size_t)bh * SEQ * DH;
    const float* Kb = g_Kp + (size_t)bh * SEQ * DH;
    const float* Vb = g_Vp + (size_t)bh * SEQ * DH;

    const uint32_t sKu = smem_u32(sKb);
    const uint32_t sVu = smem_u32(sVb);

    auto issue_kv = [&](int kt, int buf) {
        const int k0 = kt << 5;
        uint32_t kd = sKu + (uint32_t)(buf * 2176) * 4;
        uint32_t vd = sVu + (uint32_t)(buf * 2304) * 4;
#pragma unroll
        for (int r = 0; r < 4; r++) {
            int j = tid + (r << 7);
            int row = j >> 4, c4 = (j & 15) << 2;
            cp16(kd + (uint32_t)(row * 68 + c4) * 4,
                 Kb + (size_t)(k0 + row) * DH + c4);
            cp16(vd + (uint32_t)(row * 72 + c4) * 4,
                 Vb + (size_t)(k0 + row) * DH + c4);
        }
        CP_COMMIT();
    };

    // stage Q tile 128x64 into Qs in a-frag order (once per CTA)
#pragma unroll
    for (int r = 0; r < 16; r++) {
        int j = tid + (r << 7);
        int row = j >> 4, c4 = (j & 15) << 2;
        float4 vq = *(const float4*)(Qb + (size_t)(q0 + row) * DH + c4);
        int mt2 = row >> 4, rbit = (row >> 3) & 1, gg = row & 7;
        int ks = c4 >> 3, hbit = (c4 >> 2) & 1;
        int base = ((mt2 << 3) + ks) * 128 + (gg << 4) + rbit + (hbit << 1);
        Qs[base]      = vq.x;
        Qs[base + 4]  = vq.y;
        Qs[base + 8]  = vq.z;
        Qs[base + 12] = vq.w;
    }

    float o0[8][4], o1[8][4];
#pragma unroll
    for (int nt = 0; nt < 8; nt++)
#pragma unroll
        for (int c = 0; c < 4; c++) { o0[nt][c] = 0.f; o1[nt][c] = 0.f; }
    float mr[4] = {-1e30f, -1e30f, -1e30f, -1e30f};
    float lr[4] = {0.f, 0.f, 0.f, 0.f};

    const float cscale = 0.125f * 1.4426950408889634f;  // 1/sqrt(64) * log2(e)
    const int rw = w << 5;
    const int srcLo = (lane & 28) | (t >> 1);   // quad-local a-frag source lane
    const bool odd = (t & 1);

    const int ktmax = 4 * qb + 3;
    issue_kv(0, 0);

    for (int kt = 0; kt <= ktmax; kt++) {
        const int buf = kt & 1;
        if (kt < ktmax) { issue_kv(kt + 1, buf ^ 1); CP_WAIT1(); }
        else            { CP_WAIT0(); }
        __syncthreads();               // data of chunk kt visible to all warps

        const int kvb = kt << 5;
        // warp-level early-out: chunk fully above this warp's diagonal
        if (kvb <= q0 + rw + 31) {
            const float* sK = sKb + buf * 2176;
            const float* sV = sVb + buf * 2304;

            // ---- S = Q K^T (32q x 32kv per warp), ks outer, LDS.128 Q ----
            float s0[4][4], s1[4][4];
#pragma unroll
            for (int nt = 0; nt < 4; nt++)
#pragma unroll
                for (int c = 0; c < 4; c++) { s0[nt][c] = 0.f; s1[nt][c] = 0.f; }
#pragma unroll
            for (int ks = 0; ks < 8; ks++) {
                const int c = (ks << 3) + t;
                float4 qv0 = QsF4[(((w << 1) << 3) + ks) * 32 + lane];
                float4 qv1 = QsF4[((((w << 1) + 1) << 3) + ks) * 32 + lane];
                unsigned qf0[4] = {__float_as_uint(qv0.x), __float_as_uint(qv0.y),
                                   __float_as_uint(qv0.z), __float_as_uint(qv0.w)};
                unsigned qf1[4] = {__float_as_uint(qv1.x), __float_as_uint(qv1.y),
                                   __float_as_uint(qv1.z), __float_as_uint(qv1.w)};
#pragma unroll
                for (int nt = 0; nt < 4; nt++) {
                    int r = (nt << 3) + g;
                    unsigned b0 = __float_as_uint(sK[r * 68 + c]);
                    unsigned b1 = __float_as_uint(sK[r * 68 + c + 4]);
                    mma_tf32(s0[nt], qf0, b0, b1);
                    mma_tf32(s1[nt], qf1, b0, b1);
                }
            }

            // ---- scale + causal mask ----
#pragma unroll
            for (int nt = 0; nt < 4; nt++)
#pragma unroll
                for (int c = 0; c < 4; c++) { s0[nt][c] *= cscale; s1[nt][c] *= cscale; }
            if (kt >= 4 * qb) {
                const int qg0 = q0 + rw + g;
#pragma unroll
                for (int nt = 0; nt < 4; nt++) {
                    int kv = kvb + (nt << 3) + (t << 1);
                    if (kv > qg0)          s0[nt][0] = -1e30f;
                    if (kv + 1 > qg0)      s0[nt][1] = -1e30f;
                    if (kv > qg0 + 8)      s0[nt][2] = -1e30f;
                    if (kv + 1 > qg0 + 8)  s0[nt][3] = -1e30f;
                    if (kv > qg0 + 16)     s1[nt][0] = -1e30f;
                    if (kv + 1 > qg0 + 16) s1[nt][1] = -1e30f;
                    if (kv > qg0 + 24)     s1[nt][2] = -1e30f;
                    if (kv + 1 > qg0 + 24) s1[nt][3] = -1e30f;
                }
            }

            // ---- online softmax (4 row-sets), R8 form ----
#pragma unroll
            for (int sb = 0; sb < 2; sb++) {
                float (*s)[4] = sb ? s1 : s0;
                float (*o)[4] = sb ? o1 : o0;
#pragma unroll
                for (int r = 0; r < 2; r++) {
                    int ix = sb * 2 + r;
                    float mx = -1e30f;
#pragma unroll
                    for (int nt = 0; nt < 4; nt++)
                        mx = fmaxf(mx, fmaxf(s[nt][2 * r], s[nt][2 * r + 1]));
                    mx = fmaxf(mx, __shfl_xor_sync(0xffffffffu, mx, 1));
                    mx = fmaxf(mx, __shfl_xor_sync(0xffffffffu, mx, 2));
                    float mn = fmaxf(mr[ix], mx);
                    float al = ex2_(mr[ix] - mn);
                    mr[ix] = mn;
                    float rs = 0.f;
#pragma unroll
                    for (int nt = 0; nt < 4; nt++) {
                        float p0 = ex2_(s[nt][2 * r] - mn);
                        float p1 = ex2_(s[nt][2 * r + 1] - mn);
                        s[nt][2 * r] = p0; s[nt][2 * r + 1] = p1;
                        rs += p0 + p1;
                    }
                    rs += __shfl_xor_sync(0xffffffffu, rs, 1);
                    rs += __shfl_xor_sync(0xffffffffu, rs, 2);
                    lr[ix] = lr[ix] * al + rs;
#pragma unroll
                    for (int nt = 0; nt < 8; nt++) {
                        o[nt][2 * r]     *= al;
                        o[nt][2 * r + 1] *= al;
                    }
                }
            }

            // ---- O += P V : P a-frags built via quad shfl (no smem) ----
#pragma unroll
            for (int ks = 0; ks < 4; ks++) {
                unsigned pf0[4], pf1[4];
                {   // sb0: c-frag s0[ks] -> a-frag
                    float e0 = __uint_as_float(f2tf(s0[ks][0]));
                    float e1 = __uint_as_float(f2tf(s0[ks][1]));
                    float e2 = __uint_as_float(f2tf(s0[ks][2]));
                    float e3 = __uint_as_float(f2tf(s0[ks][3]));
                    float x0 = __shfl_sync(0xffffffffu, e0, srcLo);
                    float x1 = __shfl_sync(0xffffffffu, e1, srcLo);
                    float y0 = __shfl_sync(0xffffffffu, e2, srcLo);
                    float y1 = __shfl_sync(0xffffffffu, e3, srcLo);
                    float z0 = __shfl_sync(0xffffffffu, e0, srcLo + 2);
                    float z1 = __shfl_sync(0xffffffffu, e1, srcLo + 2);
                    float w0 = __shfl_sync(0xffffffffu, e2, srcLo + 2);
                    float w1 = __shfl_sync(0xffffffffu, e3, srcLo + 2);
                    pf0[0] = __float_as_uint(odd ? x1 : x0);
                    pf0[1] = __float_as_uint(odd ? y1 : y0);
                    pf0[2] = __float_as_uint(odd ? z1 : z0);
                    pf0[3] = __float_as_uint(odd ? w1 : w0);
                }
                {   // sb1: c-frag s1[ks] -> a-frag
                    float e0 = __uint_as_float(f2tf(s1[ks][0]));
                    float e1 = __uint_as_float(f2tf(s1[ks][1]));
                    float e2 = __uint_as_float(f2tf(s1[ks][2]));
                    float e3 = __uint_as_float(f2tf(s1[ks][3]));
                    float x0 = __shfl_sync(0xffffffffu, e0, srcLo);
                    float x1 = __shfl_sync(0xffffffffu, e1, srcLo);
                    float y0 = __shfl_sync(0xffffffffu, e2, srcLo);
                    float y1 = __shfl_sync(0xffffffffu, e3, srcLo);
                    float z0 = __shfl_sync(0xffffffffu, e0, srcLo + 2);
                    float z1 = __shfl_sync(0xffffffffu, e1, srcLo + 2);
                    float w0 = __shfl_sync(0xffffffffu, e2, srcLo + 2);
                    float w1 = __shfl_sync(0xffffffffu, e3, srcLo + 2);
                    pf1[0] = __float_as_uint(odd ? x1 : x0);
                    pf1[1] = __float_as_uint(odd ? y1 : y0);
                    pf1[2] = __float_as_uint(odd ? z1 : z0);
                    pf1[3] = __float_as_uint(odd ? w1 : w0);
                }
                const int kr = (ks << 3) + t;
#pragma unroll
                for (int nt = 0; nt < 8; nt++) {
                    int nc = (nt << 3) + g;
                    unsigned v0 = __float_as_uint(sV[kr * 72 + nc]);
                    unsigned v1 = __float_as_uint(sV[(kr + 4) * 72 + nc]);
                    mma_tf32(o0[nt], pf0, v0, v1);
                    mma_tf32(o1[nt], pf1, v0, v1);
                }
            }
        }
        __syncthreads();               // all reads of buf done before reuse
    }

    // ---- epilogue -> g_At [B, S, H*Dh] (plain fp32) ----
    const int b = bh >> 3, h = bh & 7;
#pragma unroll
    for (int sb = 0; sb < 2; sb++) {
        float (*o)[4] = sb ? o1 : o0;
#pragma unroll
        for (int r = 0; r < 2; r++) {
            int row = q0 + rw + (sb << 4) + (r << 3) + g;
            float inv = 1.f / lr[sb * 2 + r];
#pragma unroll
            for (int nt = 0; nt < 8; nt++) {
                int col = (h << 6) + (nt << 3) + (t << 1);
                size_t base = ((size_t)b * SEQ + row) * DM + col;
                float2 v = make_float2(o[nt][2 * r] * inv, o[nt][2 * r + 1] * inv);
                *(float2*)&g_At[base] = v;
            }
        }
    }
}

// ---------------------------------------------------------------------------
extern "C" void kernel_launch(void* const* d_in, const int* in_sizes, int n_in,
                              void* d_out, int out_size)
{
    const float* q  = (const float*)d_in[0];
    const float* k  = (const float*)d_in[1];
    const float* v  = (const float*)d_in[2];
    const float* wq = (const float*)d_in[3];
    const float* wk = (const float*)d_in[4];
    const float* wv = (const float*)d_in[5];
    const float* wo = (const float*)d_in[6];
    float* out = (float*)d_out;

    const int FLASH_SMEM = 17152 * (int)sizeof(float);   // 68608 B -> 3 CTA/SM
    cudaFuncSetAttribute(flash_tc, cudaFuncAttributeMaxDynamicSharedMemorySize,
                         FLASH_SMEM);

    dim3 pg(MTOT / 128, DM / 128, 3);        // 64 x 4 x 3
    gemm_proj<<<pg, 128>>>(q, k, v, wq, wk, wv);

    dim3 fg(SEQ / 128, BATCH * NH);          // 32 x 16
    flash_tc<<<fg, 128, FLASH_SMEM>>>();

    dim3 og(MTOT / 128, DM / 128);           // 64 x 4
    gemm_out<<<og, 128>>>(wo, out);
}